// round 7
// baseline (speedup 1.0000x reference)
#include <cuda_runtime.h>
#include <cuda_bf16.h>
#include <stdint.h>
#include <math.h>

// Problem constants
#define BN 8
#define CN 256
#define ON 256
#define HN 64
#define WN 64
#define HW 4096
#define K2 9
#define DGN 4
#define CGN 64
#define KD 2304          // CN*K2 (GEMM reduction dim)
#define GN_GROUPS 32
#define GRP_ELEMS 32768
#define EPS 1e-5f

// Batch pairing: process 2 batches at a time through a small, L2-resident
// col scratch, interleaving im2col and GEMM launches.
#define PB 2             // batches per pair
#define NPAIR (BN / PB)  // 4

// GEMM tiling
#define BM 128
#define BNT 64
#define BK 32
#define NCH (KD / BK)        // 72
#define ROWB 80              // padded SMEM row stride (bytes) for 32 bf16
#define T_A (BM * ROWB)      // 10240 B per A tile
#define T_B (BNT * ROWB)     // 5120 B per B tile
#define STAGE_B (2 * T_A + 2 * T_B)   // 30720 B per stage
#define NSTAGE 3
#define SMEM_TOTAL (NSTAGE * STAGE_B) // 92160 B

// ---------------------------------------------------------------------------
// Device scratch (col buffer sized for ONE pair: stays L2-resident)
// ---------------------------------------------------------------------------
__device__ __nv_bfloat16 g_colh[(size_t)PB * HW * KD];   // 37.75 MB
__device__ __nv_bfloat16 g_coll[(size_t)PB * HW * KD];   // 37.75 MB
__device__ __nv_bfloat16 g_wh[(size_t)ON * KD];
__device__ __nv_bfloat16 g_wl[(size_t)ON * KD];
__device__ float g_mu[BN * GN_GROUPS];
__device__ float g_rstd[BN * GN_GROUPS];

// ---------------------------------------------------------------------------
// PTX helpers (stable sm_80+ features only)
// ---------------------------------------------------------------------------
__device__ __forceinline__ uint32_t smem_u32(const void* p) {
    uint32_t a;
    asm("{ .reg .u64 t; cvta.to.shared.u64 t, %1; cvt.u32.u64 %0, t; }"
        : "=r"(a) : "l"(p));
    return a;
}
__device__ __forceinline__ void cp16(uint32_t s, const void* g) {
    asm volatile("cp.async.cg.shared.global [%0], [%1], 16;"
                 :: "r"(s), "l"(g) : "memory");
}
#define CP_COMMIT() asm volatile("cp.async.commit_group;" ::: "memory")
#define CP_WAIT(n)  asm volatile("cp.async.wait_group %0;" :: "n"(n) : "memory")

__device__ __forceinline__ void ldm_x4(uint32_t* r, uint32_t addr) {
    asm volatile("ldmatrix.sync.aligned.m8n8.x4.shared.b16 {%0,%1,%2,%3}, [%4];"
                 : "=r"(r[0]), "=r"(r[1]), "=r"(r[2]), "=r"(r[3]) : "r"(addr));
}
__device__ __forceinline__ void mma_bf16(float* c, const uint32_t* a,
                                         const uint32_t* b) {
    asm volatile(
        "mma.sync.aligned.m16n8k16.row.col.f32.bf16.bf16.f32 "
        "{%0,%1,%2,%3}, {%4,%5,%6,%7}, {%8,%9}, {%0,%1,%2,%3};"
        : "+f"(c[0]), "+f"(c[1]), "+f"(c[2]), "+f"(c[3])
        : "r"(a[0]), "r"(a[1]), "r"(a[2]), "r"(a[3]), "r"(b[0]), "r"(b[1]));
}

// ---------------------------------------------------------------------------
// Kernel A: split weights into bf16 hi/lo. w flat [O][KD], kd = c*9+ky*3+kx.
// ---------------------------------------------------------------------------
__global__ void wsplit_kernel(const float* __restrict__ w)
{
    int i = blockIdx.x * blockDim.x + threadIdx.x;
    float v = w[i];
    __nv_bfloat16 h = __float2bfloat16(v);
    __nv_bfloat16 l = __float2bfloat16(v - __bfloat162float(h));
    g_wh[i] = h;
    g_wl[i] = l;
}

// ---------------------------------------------------------------------------
// Kernel B (v3): fused offset-projection + deformable im2col with SMEM-staged
// transpose. Operates on ONE batch pair: xp/xop are pre-offset to the pair,
// blockIdx.z = local batch (0..PB-1). Output layout: col[bl][hw][kd],
// kd = g*576 + c*9 + k, as bf16 hi/lo. (Validated math.)
// ---------------------------------------------------------------------------
#define V3HW 16
#define QP   288               // kd pairs per (g) slice: 576/2
#define SROW 289               // uint32 row stride (289 mod 32 == 1)
__global__ void __launch_bounds__(256)
im2col3_kernel(const float* __restrict__ xp,
               const float* __restrict__ xop,
               const float* __restrict__ w_offset)
{
    const int bl  = blockIdx.z;           // local batch within pair
    const int g   = blockIdx.y;
    const int hw0 = blockIdx.x * V3HW;
    const int tid = threadIdx.x;

    __shared__ int      s_i[4][V3HW * 9];
    __shared__ float    s_w[4][V3HW * 9];
    __shared__ uint32_t s_h[V3HW * SROW];    // packed bf16x2 (kd even, kd odd)
    __shared__ uint32_t s_l[V3HW * SROW];

    // Phase 1: bilinear params for 16 hw x 9 k
    if (tid < V3HW * 9) {
        int p   = tid;
        int hwl = p / 9;
        int k   = p - hwl * 9;
        int hw  = hw0 + hwl;
        int h = hw >> 6, w = hw & 63;

        const float* xo = xop + (size_t)bl * 4 * HW + hw;
        float o0 = xo[0], o1 = xo[HW], o2 = xo[2 * HW], o3 = xo[3 * HW];
        const float* wo = w_offset + (size_t)((g * K2 + k) * 2) * 4;
        float offy = wo[0] * o0 + wo[1] * o1 + wo[2] * o2 + wo[3] * o3;
        float offx = wo[4] * o0 + wo[5] * o1 + wo[6] * o2 + wo[7] * o3;

        float py = (float)(h + k / 3 - 1) + offy;
        float px = (float)(w + k % 3 - 1) + offx;
        float fy = floorf(py), fx = floorf(px);
        int y0 = (int)fy, x0 = (int)fx, y1 = y0 + 1, x1 = x0 + 1;
        float wy = py - fy, wx = px - fx;

        float my0 = (y0 >= 0 && y0 < HN) ? 1.f : 0.f;
        float my1 = (y1 >= 0 && y1 < HN) ? 1.f : 0.f;
        float mx0 = (x0 >= 0 && x0 < WN) ? 1.f : 0.f;
        float mx1 = (x1 >= 0 && x1 < WN) ? 1.f : 0.f;
        int y0c = min(max(y0, 0), HN - 1), y1c = min(max(y1, 0), HN - 1);
        int x0c = min(max(x0, 0), WN - 1), x1c = min(max(x1, 0), WN - 1);

        s_i[0][p] = y0c * WN + x0c;
        s_i[1][p] = y0c * WN + x1c;
        s_i[2][p] = y1c * WN + x0c;
        s_i[3][p] = y1c * WN + x1c;
        s_w[0][p] = (1.f - wy) * (1.f - wx) * my0 * mx0;
        s_w[1][p] = (1.f - wy) * wx          * my0 * mx1;
        s_w[2][p] = wy * (1.f - wx)          * my1 * mx0;
        s_w[3][p] = wy * wx                  * my1 * mx1;
    }
    __syncthreads();

    const float* xg = xp + ((size_t)(bl * CN + g * CGN)) * HW;

    // Phase 2: 18 iters; half-warp = one kd-pair (c0,k0 / c1,k1), 16 hw lanes.
    #pragma unroll 2
    for (int i = 0; i < 18; i++) {
        int qp  = i * 16 + (tid >> 4);     // 0..287
        int hwl = tid & 15;
        int kd0 = qp * 2;
        int c0 = kd0 / 9, k0 = kd0 - 9 * c0;
        int kd1 = kd0 + 1;
        int c1 = kd1 / 9, k1 = kd1 - 9 * c1;

        int pa = hwl * 9 + k0;
        int pb = hwl * 9 + k1;
        const float* xc0 = xg + (size_t)c0 * HW;
        const float* xc1 = xg + (size_t)c1 * HW;

        float v0 = s_w[0][pa] * xc0[s_i[0][pa]] + s_w[1][pa] * xc0[s_i[1][pa]] +
                   s_w[2][pa] * xc0[s_i[2][pa]] + s_w[3][pa] * xc0[s_i[3][pa]];
        float v1 = s_w[0][pb] * xc1[s_i[0][pb]] + s_w[1][pb] * xc1[s_i[1][pb]] +
                   s_w[2][pb] * xc1[s_i[2][pb]] + s_w[3][pb] * xc1[s_i[3][pb]];

        __nv_bfloat16 h0 = __float2bfloat16(v0);
        __nv_bfloat16 l0 = __float2bfloat16(v0 - __bfloat162float(h0));
        __nv_bfloat16 h1 = __float2bfloat16(v1);
        __nv_bfloat16 l1 = __float2bfloat16(v1 - __bfloat162float(h1));

        uint32_t ph = ((uint32_t)__bfloat16_as_ushort(h1) << 16) |
                       (uint32_t)__bfloat16_as_ushort(h0);
        uint32_t pl = ((uint32_t)__bfloat16_as_ushort(l1) << 16) |
                       (uint32_t)__bfloat16_as_ushort(l0);
        s_h[hwl * SROW + qp] = ph;
        s_l[hwl * SROW + qp] = pl;
    }
    __syncthreads();

    // Phase 3: coalesced writeout, 288-word (1152B) bursts per hw row.
    uint32_t* gh = (uint32_t*)(g_colh + ((size_t)bl * HW) * KD + (size_t)g * 576);
    uint32_t* gl = (uint32_t*)(g_coll + ((size_t)bl * HW) * KD + (size_t)g * 576);
    for (int idx = tid; idx < V3HW * QP; idx += 256) {
        int hwl = idx / QP;
        int q   = idx - hwl * QP;
        size_t goff = (size_t)(hw0 + hwl) * (KD / 2) + q;
        gh[goff] = s_h[hwl * SROW + q];
        gl[goff] = s_l[hwl * SROW + q];
    }
}

// ---------------------------------------------------------------------------
// Kernel C: mma.sync bf16 split GEMM (validated mainloop/epilogue math).
// 3-stage cp.async pipeline, ONE __syncthreads per chunk (stage being read
// is rewritten only two iterations later, ordered by the next barrier).
// Operates on one batch pair: outp pre-offset, blockIdx.z = local batch.
// ---------------------------------------------------------------------------
__global__ void __launch_bounds__(256, 2)
gemm_mma_kernel(float* __restrict__ outp)
{
    extern __shared__ char smem[];
    const uint32_t sb = smem_u32(smem);
    const int tid = threadIdx.x;
    const int wid = tid >> 5, lane = tid & 31;
    const int warp_m = wid & 3;
    const int warp_n = wid >> 2;
    const int m0 = blockIdx.x * BM;      // m fastest: pair m-tiles share B in L2
    const int n0 = blockIdx.y * BNT;
    const int bl = blockIdx.z;

    const __nv_bfloat16* Ah = g_wh + (size_t)m0 * KD;
    const __nv_bfloat16* Al = g_wl + (size_t)m0 * KD;
    const __nv_bfloat16* Bh = g_colh + ((size_t)(bl * HW + n0)) * KD;
    const __nv_bfloat16* Bl = g_coll + ((size_t)(bl * HW + n0)) * KD;

    const int arow0 = tid >> 2,         acs0 = (tid & 3);
    const int arow1 = (tid + 256) >> 2, acs1 = (tid & 3);
    const int brow = tid >> 2, bcs = (tid & 3);

    float c[2][4][4];
    #pragma unroll
    for (int i = 0; i < 2; i++)
        #pragma unroll
        for (int j = 0; j < 4; j++)
            #pragma unroll
            for (int q = 0; q < 4; q++) c[i][j][q] = 0.f;

    // stage loader
    auto load_chunk = [&](int ch, int stg) {
        const int k0 = ch * BK;
        uint32_t st = sb + stg * STAGE_B;
        cp16(st + 0 * T_A + arow0 * ROWB + acs0 * 16, Ah + (size_t)arow0 * KD + k0 + acs0 * 8);
        cp16(st + 0 * T_A + arow1 * ROWB + acs1 * 16, Ah + (size_t)arow1 * KD + k0 + acs1 * 8);
        cp16(st + 1 * T_A + arow0 * ROWB + acs0 * 16, Al + (size_t)arow0 * KD + k0 + acs0 * 8);
        cp16(st + 1 * T_A + arow1 * ROWB + acs1 * 16, Al + (size_t)arow1 * KD + k0 + acs1 * 8);
        cp16(st + 2 * T_A + brow * ROWB + bcs * 16,   Bh + (size_t)brow * KD + k0 + bcs * 8);
        cp16(st + 2 * T_A + T_B + brow * ROWB + bcs * 16, Bl + (size_t)brow * KD + k0 + bcs * 8);
        CP_COMMIT();
    };

    load_chunk(0, 0);

    for (int ch = 0; ch < NCH; ch++) {
        if (ch + 1 < NCH) {
            load_chunk(ch + 1, (ch + 1) % NSTAGE);
            CP_WAIT(1);
        } else {
            CP_WAIT(0);
        }
        __syncthreads();

        const uint32_t st = sb + (ch % NSTAGE) * STAGE_B;
        #pragma unroll
        for (int ks = 0; ks < 2; ks++) {
            uint32_t a_off = (uint32_t)((warp_m * 32 + (lane & 15)) * ROWB
                                        + ks * 32 + ((lane >> 4) << 4));
            uint32_t ah[2][4], al[2][4];
            #pragma unroll
            for (int mf = 0; mf < 2; mf++) {
                ldm_x4(ah[mf], st + 0 * T_A + a_off + mf * 16 * ROWB);
                ldm_x4(al[mf], st + 1 * T_A + a_off + mf * 16 * ROWB);
            }
            uint32_t b_off = (uint32_t)((warp_n * 32 + (lane & 7) + ((lane >> 4) << 3)) * ROWB
                                        + ks * 32 + (((lane >> 3) & 1) << 4));
            uint32_t bh[4][2], bl[4][2];
            #pragma unroll
            for (int nfp = 0; nfp < 2; nfp++) {
                uint32_t r[4];
                ldm_x4(r, st + 2 * T_A + b_off + nfp * 16 * ROWB);
                bh[nfp * 2][0] = r[0]; bh[nfp * 2][1] = r[1];
                bh[nfp * 2 + 1][0] = r[2]; bh[nfp * 2 + 1][1] = r[3];
                ldm_x4(r, st + 2 * T_A + T_B + b_off + nfp * 16 * ROWB);
                bl[nfp * 2][0] = r[0]; bl[nfp * 2][1] = r[1];
                bl[nfp * 2 + 1][0] = r[2]; bl[nfp * 2 + 1][1] = r[3];
            }
            #pragma unroll
            for (int mf = 0; mf < 2; mf++)
                #pragma unroll
                for (int nf = 0; nf < 4; nf++) {
                    mma_bf16(c[mf][nf], ah[mf], bh[nf]);
                    mma_bf16(c[mf][nf], ah[mf], bl[nf]);
                    mma_bf16(c[mf][nf], al[mf], bh[nf]);
                }
        }
    }

    #pragma unroll
    for (int mf = 0; mf < 2; mf++)
        #pragma unroll
        for (int nf = 0; nf < 4; nf++) {
            int row = m0 + warp_m * 32 + mf * 16 + (lane >> 2);
            int col = n0 + warp_n * 32 + nf * 8 + 2 * (lane & 3);
            float* op0 = outp + ((size_t)(bl * ON + row)) * HW + col;
            float* op1 = outp + ((size_t)(bl * ON + row + 8)) * HW + col;
            *(float2*)op0 = make_float2(c[mf][nf][0], c[mf][nf][1]);
            *(float2*)op1 = make_float2(c[mf][nf][2], c[mf][nf][3]);
        }
}

// ---------------------------------------------------------------------------
// GroupNorm stats + normalize (validated)
// ---------------------------------------------------------------------------
__global__ void gn_stats_kernel(const float* __restrict__ y)
{
    const int bg = blockIdx.x;
    const float* p = y + (size_t)bg * GRP_ELEMS;
    float s = 0.f, ss = 0.f;
    for (int i = threadIdx.x * 4; i < GRP_ELEMS; i += blockDim.x * 4) {
        float4 v = *(const float4*)(p + i);
        s  += v.x + v.y + v.z + v.w;
        ss += v.x * v.x + v.y * v.y + v.z * v.z + v.w * v.w;
    }
    #pragma unroll
    for (int off = 16; off > 0; off >>= 1) {
        s  += __shfl_down_sync(0xffffffffu, s,  off);
        ss += __shfl_down_sync(0xffffffffu, ss, off);
    }
    __shared__ float sh_s[8], sh_ss[8];
    int wid = threadIdx.x >> 5, lid = threadIdx.x & 31;
    if (lid == 0) { sh_s[wid] = s; sh_ss[wid] = ss; }
    __syncthreads();
    if (wid == 0) {
        s  = (lid < 8) ? sh_s[lid]  : 0.f;
        ss = (lid < 8) ? sh_ss[lid] : 0.f;
        #pragma unroll
        for (int off = 4; off > 0; off >>= 1) {
            s  += __shfl_down_sync(0xffffffffu, s,  off);
            ss += __shfl_down_sync(0xffffffffu, ss, off);
        }
        if (lid == 0) {
            float mu  = s * (1.f / GRP_ELEMS);
            float var = ss * (1.f / GRP_ELEMS) - mu * mu;
            g_mu[bg]   = mu;
            g_rstd[bg] = rsqrtf(var + EPS);
        }
    }
}

__global__ void gn_norm_kernel(float* __restrict__ y,
                               const float* __restrict__ gamma,
                               const float* __restrict__ beta)
{
    int idx = blockIdx.x * blockDim.x + threadIdx.x;
    int bg = idx >> 13;
    int c  = (idx >> 10) & 255;
    float mu = g_mu[bg];
    float r  = g_rstd[bg];
    float a  = r * gamma[c];
    float bb = beta[c] - mu * a;
    float4 v = *(float4*)(y + (size_t)idx * 4);
    v.x = fmaxf(fmaf(v.x, a, bb), 0.f);
    v.y = fmaxf(fmaf(v.y, a, bb), 0.f);
    v.z = fmaxf(fmaf(v.z, a, bb), 0.f);
    v.w = fmaxf(fmaf(v.w, a, bb), 0.f);
    *(float4*)(y + (size_t)idx * 4) = v;
}

// ---------------------------------------------------------------------------
// Launcher: batch-paired im2col/GEMM interleave keeps col in L2.
// ---------------------------------------------------------------------------
extern "C" void kernel_launch(void* const* d_in, const int* in_sizes, int n_in,
                              void* d_out, int out_size)
{
    const float* x        = (const float*)d_in[0];
    const float* x_off    = (const float*)d_in[1];
    const float* w_offset = (const float*)d_in[2];
    const float* w_deform = (const float*)d_in[3];
    const float* gamma    = (const float*)d_in[4];
    const float* beta     = (const float*)d_in[5];
    float* out = (float*)d_out;

    cudaFuncSetAttribute(gemm_mma_kernel,
                         cudaFuncAttributeMaxDynamicSharedMemorySize,
                         SMEM_TOTAL);

    // 1) weight split
    wsplit_kernel<<<(ON * KD) / 256, 256>>>(w_deform);

    // 2+3) per-pair im2col -> GEMM (col scratch reused; L2-resident)
    for (int p = 0; p < NPAIR; p++) {
        const float* xp  = x     + (size_t)p * PB * CN * HW;
        const float* xop = x_off + (size_t)p * PB * 4 * HW;
        float* outp      = out   + (size_t)p * PB * ON * HW;

        dim3 gi(HW / V3HW, DGN, PB);         // (256, 4, 2)
        im2col3_kernel<<<gi, 256>>>(xp, xop, w_offset);

        dim3 gg(ON / BM, HW / BNT, PB);      // (2, 64, 2)
        gemm_mma_kernel<<<gg, 256, SMEM_TOTAL>>>(outp);
    }

    // 4) GroupNorm
    gn_stats_kernel<<<BN * GN_GROUPS, 256>>>(out);
    gn_norm_kernel<<<(BN * ON * HW / 4) / 256, 256>>>(out, gamma, beta);
}